// round 1
// baseline (speedup 1.0000x reference)
#include <cuda_runtime.h>
#include <cstdint>

// Problem constants (fixed shapes for HRTExtractor_81320910782627)
#define N_DOCS 4
#define LSEQ   1024
#define DMODEL 768
#define NHEAD  12
#define NE     32
#define NM     4
#define NR     256
#define POS_OFFSET 1

#define NEG_INF (-3.402823466e38f)

// Scratch (device globals: no allocation allowed in kernel_launch)
__device__ float g_eemb[N_DOCS * NE * DMODEL];          // (i,e,d)
__device__ float g_eatt[N_DOCS * NE * NHEAD * LSEQ];    // (i,e,h,l)
__device__ float g_ht  [N_DOCS * NR * LSEQ];            // (i,r,l) normalized

// ---------------------------------------------------------------------------
// Kernel 1: e_emb = logsumexp over M masked mention embeddings
// grid: N_DOCS*NE blocks, 256 threads
// ---------------------------------------------------------------------------
__global__ __launch_bounds__(256) void k_eemb(
    const float* __restrict__ seq,      // (n, L, d)
    const int*   __restrict__ mpos,     // (n, E, M)
    const float* __restrict__ mmask)    // (n, E, M)
{
    int ie = blockIdx.x;                // i*NE + e
    int i  = ie / NE;

    __shared__ int   sp[NM];
    __shared__ float sm[NM];
    if (threadIdx.x < NM) {
        sp[threadIdx.x] = mpos[ie * NM + threadIdx.x] + POS_OFFSET;
        sm[threadIdx.x] = mmask[ie * NM + threadIdx.x];
    }
    __syncthreads();

    for (int dd = threadIdx.x; dd < DMODEL; dd += blockDim.x) {
        float v[NM];
        float mx = NEG_INF;
        #pragma unroll
        for (int m = 0; m < NM; m++) {
            float x = (sm[m] > 0.f)
                ? seq[((size_t)i * LSEQ + sp[m]) * DMODEL + dd]
                : NEG_INF;
            v[m] = x;
            mx = fmaxf(mx, x);
        }
        float s = 0.f;
        #pragma unroll
        for (int m = 0; m < NM; m++) s += expf(v[m] - mx);
        g_eemb[(size_t)ie * DMODEL + dd] = logf(s) + mx;
    }
}

// ---------------------------------------------------------------------------
// Kernel 2: e_att[i,e,h,l] = sum_m mask*att[i,h,pos,l] / max(sum_m mask, 1)
// grid: N_DOCS*NE*NHEAD blocks, 256 threads, each thread one float4 of l
// ---------------------------------------------------------------------------
__global__ __launch_bounds__(256) void k_eatt(
    const float* __restrict__ att,      // (n, h, L, L)
    const int*   __restrict__ mpos,
    const float* __restrict__ mmask)
{
    int b  = blockIdx.x;                // (i*NE+e)*NHEAD + hh
    int hh = b % NHEAD;
    int ie = b / NHEAD;
    int i  = ie / NE;

    int   p[NM];
    float mk[NM];
    float cnt = 0.f;
    #pragma unroll
    for (int m = 0; m < NM; m++) {
        p[m]  = mpos[ie * NM + m] + POS_OFFSET;
        mk[m] = mmask[ie * NM + m];
        cnt += mk[m];
    }
    float inv = 1.f / fmaxf(cnt, 1.f);

    int l4 = threadIdx.x * 4;           // 256 threads * 4 = 1024 = LSEQ
    float4 acc = make_float4(0.f, 0.f, 0.f, 0.f);
    #pragma unroll
    for (int m = 0; m < NM; m++) {
        const float4 a = *(const float4*)&att[
            (((size_t)i * NHEAD + hh) * LSEQ + p[m]) * LSEQ + l4];
        acc.x += mk[m] * a.x; acc.y += mk[m] * a.y;
        acc.z += mk[m] * a.z; acc.w += mk[m] * a.w;
    }
    float4 o = make_float4(acc.x * inv, acc.y * inv, acc.z * inv, acc.w * inv);
    *(float4*)&g_eatt[((size_t)ie * NHEAD + hh) * LSEQ + l4] = o;
}

// ---------------------------------------------------------------------------
// Kernel 3: hs/ts gather into out[0], out[1]
// grid: N_DOCS*NR blocks, 256 threads
// ---------------------------------------------------------------------------
__global__ __launch_bounds__(256) void k_hsts(
    const int* __restrict__ hts,        // (n, R, 2)
    float* __restrict__ out)
{
    int b = blockIdx.x;                 // i*NR + r
    int i = b / NR;
    int e0 = hts[b * 2 + 0];
    int e1 = hts[b * 2 + 1];
    const float* eh = &g_eemb[(size_t)(i * NE + e0) * DMODEL];
    const float* et = &g_eemb[(size_t)(i * NE + e1) * DMODEL];
    float* o0 = out + (size_t)b * DMODEL;
    float* o1 = out + ((size_t)N_DOCS * NR + b) * DMODEL;
    for (int dd = threadIdx.x; dd < DMODEL; dd += blockDim.x) {
        o0[dd] = eh[dd];
        o1[dd] = et[dd];
    }
}

// ---------------------------------------------------------------------------
// Kernel 4: ht_att[i,r,l] = mean_h(e_att[e0,h,l]*e_att[e1,h,l]), normalized
// over l with +1e-5. grid: N_DOCS*NR blocks, 256 threads (4 l each)
// ---------------------------------------------------------------------------
__global__ __launch_bounds__(256) void k_htatt(
    const int* __restrict__ hts)
{
    int b = blockIdx.x;                 // i*NR + r
    int i = b / NR;
    int e0 = hts[b * 2 + 0];
    int e1 = hts[b * 2 + 1];
    const float* a0 = &g_eatt[(size_t)(i * NE + e0) * NHEAD * LSEQ];
    const float* a1 = &g_eatt[(size_t)(i * NE + e1) * NHEAD * LSEQ];

    float v[4];
    float tsum = 0.f;
    #pragma unroll
    for (int j = 0; j < 4; j++) {
        int l = threadIdx.x + j * 256;
        float acc = 0.f;
        #pragma unroll
        for (int hh = 0; hh < NHEAD; hh++)
            acc += a0[hh * LSEQ + l] * a1[hh * LSEQ + l];
        v[j] = acc * (1.f / NHEAD);
        tsum += v[j];
    }

    __shared__ float red[8];
    #pragma unroll
    for (int o = 16; o; o >>= 1) tsum += __shfl_xor_sync(0xffffffffu, tsum, o);
    if ((threadIdx.x & 31) == 0) red[threadIdx.x >> 5] = tsum;
    __syncthreads();
    if (threadIdx.x < 32) {
        float x = (threadIdx.x < 8) ? red[threadIdx.x] : 0.f;
        #pragma unroll
        for (int o = 4; o; o >>= 1) x += __shfl_xor_sync(0xffffffffu, x, o);
        if (threadIdx.x == 0) red[0] = x;
    }
    __syncthreads();
    float scale = 1.f / (red[0] + 1e-5f);

    #pragma unroll
    for (int j = 0; j < 4; j++)
        g_ht[(size_t)b * LSEQ + threadIdx.x + j * 256] = v[j] * scale;
}

// ---------------------------------------------------------------------------
// Kernel 5: rs[i] = ht[i] (R x L) @ seq[i] (L x D)  -> out[2]
// BM=64, BN=96, BK=16, TM=4, TN=6, 256 threads.
// Grid = (D/96=8, R/64=4, n=4) = 128 blocks = single wave, 1 block/SM.
// ---------------------------------------------------------------------------
#define GBM 64
#define GBN 96
#define GBK 16

__global__ __launch_bounds__(256) void k_gemm(
    const float* __restrict__ seq,      // (n, L, d)
    float* __restrict__ out)
{
    int i       = blockIdx.z;
    int rowBase = blockIdx.y * GBM;
    int colBase = blockIdx.x * GBN;

    const float* A = g_ht + (size_t)i * NR * LSEQ;      // R x L row-major
    const float* B = seq + (size_t)i * LSEQ * DMODEL;   // L x D row-major

    __shared__ float As[GBM][GBK];
    __shared__ float Bs[GBK][GBN];

    int tid = threadIdx.x;
    int ty = tid >> 4;                  // 0..15 -> M rows (x4)
    int tx = tid & 15;                  // 0..15 -> N cols (x6)
    int ty4 = ty * 4;
    int tx6 = tx * 6;

    float acc[4][6];
    #pragma unroll
    for (int jm = 0; jm < 4; jm++)
        #pragma unroll
        for (int jn = 0; jn < 6; jn++) acc[jm][jn] = 0.f;

    for (int kk = 0; kk < LSEQ; kk += GBK) {
        // Load A tile: 64x16 = 256 float4 (1 per thread)
        {
            int m  = tid >> 2;
            int kq = (tid & 3) << 2;
            float4 a4 = *(const float4*)&A[(size_t)(rowBase + m) * LSEQ + kk + kq];
            *(float4*)&As[m][kq] = a4;
        }
        // Load B tile: 16x96 = 384 float4 (256 + 128)
        {
            #pragma unroll
            for (int idx = tid; idx < 384; idx += 256) {
                int kr = idx / 24;
                int c4 = (idx % 24) << 2;
                *(float4*)&Bs[kr][c4] =
                    *(const float4*)&B[(size_t)(kk + kr) * DMODEL + colBase + c4];
            }
        }
        __syncthreads();

        #pragma unroll
        for (int k = 0; k < GBK; k++) {
            float a0 = As[ty4 + 0][k];
            float a1 = As[ty4 + 1][k];
            float a2 = As[ty4 + 2][k];
            float a3 = As[ty4 + 3][k];
            float bb[6];
            #pragma unroll
            for (int jn = 0; jn < 6; jn++) bb[jn] = Bs[k][tx6 + jn];
            #pragma unroll
            for (int jn = 0; jn < 6; jn++) {
                acc[0][jn] += a0 * bb[jn];
                acc[1][jn] += a1 * bb[jn];
                acc[2][jn] += a2 * bb[jn];
                acc[3][jn] += a3 * bb[jn];
            }
        }
        __syncthreads();
    }

    // rs block of output: out[2] base
    float* O = out + ((size_t)2 * N_DOCS * NR + (size_t)i * NR) * DMODEL;
    #pragma unroll
    for (int jm = 0; jm < 4; jm++) {
        float* Orow = O + (size_t)(rowBase + ty4 + jm) * DMODEL + colBase + tx6;
        #pragma unroll
        for (int jn = 0; jn < 6; jn++) Orow[jn] = acc[jm][jn];
    }
}

// ---------------------------------------------------------------------------
extern "C" void kernel_launch(void* const* d_in, const int* in_sizes, int n_in,
                              void* d_out, int out_size)
{
    const float* seq   = (const float*)d_in[0];   // (4,1024,768) f32
    const float* att   = (const float*)d_in[1];   // (4,12,1024,1024) f32
    const int*   mpos  = (const int*)  d_in[2];   // (4,32,4) i32
    const float* mmask = (const float*)d_in[3];   // (4,32,4) f32
    const int*   hts   = (const int*)  d_in[4];   // (4,256,2) i32
    float* out = (float*)d_out;                   // (3, 4*256, 768) f32

    k_eemb <<<N_DOCS * NE,          256>>>(seq, mpos, mmask);
    k_eatt <<<N_DOCS * NE * NHEAD,  256>>>(att, mpos, mmask);
    k_hsts <<<N_DOCS * NR,          256>>>(hts, out);
    k_htatt<<<N_DOCS * NR,          256>>>(hts);
    k_gemm <<<dim3(DMODEL / GBN, NR / GBM, N_DOCS), 256>>>(seq, out);
}

// round 4
// speedup vs baseline: 1.9890x; 1.9890x over previous
#include <cuda_runtime.h>
#include <cuda_bf16.h>
#include <cstdint>

// Fixed shapes for HRTExtractor_81320910782627
#define N_DOCS 4
#define LSEQ   1024
#define DMODEL 768
#define NHEAD  12
#define NE     32
#define NM     4
#define NR     256
#define POS_OFFSET 1
#define NEG_INF (-3.402823466e38f)

// Scratch (device globals; allocation forbidden)
__device__ float    g_eemb[N_DOCS * NE * DMODEL];          // (i,e,d)
__device__ float    g_eatt[N_DOCS * NE * NHEAD * LSEQ];    // (i,e,h,l)
__device__ unsigned g_htp_hi[N_DOCS * NR * (LSEQ / 2)];    // packed bf16x2 hi, (b, l2)
__device__ unsigned g_htp_lo[N_DOCS * NR * (LSEQ / 2)];    // packed bf16x2 lo

// ---------------------------------------------------------------------------
// helpers: bf16 split + pack
// ---------------------------------------------------------------------------
__device__ __forceinline__ void bsplit(float x, float& hi, float& lo) {
    __nv_bfloat16 h = __float2bfloat16(x);
    float hf = __bfloat162float(h);
    hi = hf;
    lo = x - hf;
}
__device__ __forceinline__ unsigned pack2(float a, float b) {
    __nv_bfloat162 v = __floats2bfloat162_rn(a, b);   // .x = a (low), .y = b (high)
    return *reinterpret_cast<unsigned*>(&v);
}

// ---------------------------------------------------------------------------
// Kernel 1 (fused): blocks [0,1536) -> e_att, blocks [1536,1664) -> e_emb
// ---------------------------------------------------------------------------
__global__ __launch_bounds__(256) void k_prep(
    const float* __restrict__ seq,      // (n, L, d)
    const float* __restrict__ att,      // (n, h, L, L)
    const int*   __restrict__ mpos,     // (n, E, M)
    const float* __restrict__ mmask)    // (n, E, M)
{
    if (blockIdx.x < N_DOCS * NE * NHEAD) {
        // ---- e_att ----
        int b  = blockIdx.x;
        int hh = b % NHEAD;
        int ie = b / NHEAD;
        int i  = ie / NE;

        int   p[NM];
        float mk[NM];
        float cnt = 0.f;
        #pragma unroll
        for (int m = 0; m < NM; m++) {
            p[m]  = mpos[ie * NM + m] + POS_OFFSET;
            mk[m] = mmask[ie * NM + m];
            cnt += mk[m];
        }
        float inv = 1.f / fmaxf(cnt, 1.f);

        int l4 = threadIdx.x * 4;
        float4 acc = make_float4(0.f, 0.f, 0.f, 0.f);
        #pragma unroll
        for (int m = 0; m < NM; m++) {
            const float4 a = *(const float4*)&att[
                (((size_t)i * NHEAD + hh) * LSEQ + p[m]) * LSEQ + l4];
            acc.x += mk[m] * a.x; acc.y += mk[m] * a.y;
            acc.z += mk[m] * a.z; acc.w += mk[m] * a.w;
        }
        float4 o = make_float4(acc.x * inv, acc.y * inv, acc.z * inv, acc.w * inv);
        *(float4*)&g_eatt[((size_t)ie * NHEAD + hh) * LSEQ + l4] = o;
    } else {
        // ---- e_emb (logsumexp over M) ----
        int ie = blockIdx.x - N_DOCS * NE * NHEAD;
        int i  = ie / NE;

        __shared__ int   sp[NM];
        __shared__ float sm[NM];
        if (threadIdx.x < NM) {
            sp[threadIdx.x] = mpos[ie * NM + threadIdx.x] + POS_OFFSET;
            sm[threadIdx.x] = mmask[ie * NM + threadIdx.x];
        }
        __syncthreads();

        for (int dd = threadIdx.x; dd < DMODEL; dd += blockDim.x) {
            float v[NM];
            float mx = NEG_INF;
            #pragma unroll
            for (int m = 0; m < NM; m++) {
                float x = (sm[m] > 0.f)
                    ? seq[((size_t)i * LSEQ + sp[m]) * DMODEL + dd]
                    : NEG_INF;
                v[m] = x;
                mx = fmaxf(mx, x);
            }
            float s = 0.f;
            #pragma unroll
            for (int m = 0; m < NM; m++) s += expf(v[m] - mx);
            g_eemb[(size_t)ie * DMODEL + dd] = logf(s) + mx;
        }
    }
}

// ---------------------------------------------------------------------------
// Kernel 2 (fused): ht_att (normalized, written as packed bf16 hi/lo) + hs/ts
// grid: N_DOCS*NR blocks, 256 threads. Thread t handles l = 4t..4t+3 (float4).
// ---------------------------------------------------------------------------
__global__ __launch_bounds__(256) void k_htatt(
    const int* __restrict__ hts,        // (n, R, 2)
    float* __restrict__ out)
{
    int b = blockIdx.x;                 // i*NR + r
    int i = b / NR;
    int e0 = hts[b * 2 + 0];
    int e1 = hts[b * 2 + 1];
    const float* a0 = &g_eatt[(size_t)(i * NE + e0) * NHEAD * LSEQ];
    const float* a1 = &g_eatt[(size_t)(i * NE + e1) * NHEAD * LSEQ];

    int l4 = threadIdx.x * 4;
    float4 acc = make_float4(0.f, 0.f, 0.f, 0.f);
    #pragma unroll
    for (int hh = 0; hh < NHEAD; hh++) {
        const float4 x = *(const float4*)&a0[hh * LSEQ + l4];
        const float4 y = *(const float4*)&a1[hh * LSEQ + l4];
        acc.x += x.x * y.x; acc.y += x.y * y.y;
        acc.z += x.z * y.z; acc.w += x.w * y.w;
    }
    const float invH = 1.f / NHEAD;
    acc.x *= invH; acc.y *= invH; acc.z *= invH; acc.w *= invH;
    float tsum = acc.x + acc.y + acc.z + acc.w;

    __shared__ float red[8];
    #pragma unroll
    for (int o = 16; o; o >>= 1) tsum += __shfl_xor_sync(0xffffffffu, tsum, o);
    if ((threadIdx.x & 31) == 0) red[threadIdx.x >> 5] = tsum;
    __syncthreads();
    if (threadIdx.x < 32) {
        float x = (threadIdx.x < 8) ? red[threadIdx.x] : 0.f;
        #pragma unroll
        for (int o = 4; o; o >>= 1) x += __shfl_xor_sync(0xffffffffu, x, o);
        if (threadIdx.x == 0) red[0] = x;
    }
    __syncthreads();
    float scale = 1.f / (red[0] + 1e-5f);

    float w0 = acc.x * scale, w1 = acc.y * scale;
    float w2 = acc.z * scale, w3 = acc.w * scale;
    float h0, l0, h1, l1, h2, l2v, h3, l3;
    bsplit(w0, h0, l0); bsplit(w1, h1, l1);
    bsplit(w2, h2, l2v); bsplit(w3, h3, l3);
    unsigned base = (unsigned)b * (LSEQ / 2) + threadIdx.x * 2;
    g_htp_hi[base + 0] = pack2(h0, h1);
    g_htp_hi[base + 1] = pack2(h2, h3);
    g_htp_lo[base + 0] = pack2(l0, l1);
    g_htp_lo[base + 1] = pack2(l2v, l3);

    // hs/ts gather (same (b, e0, e1) indices)
    const float* eh = &g_eemb[(size_t)(i * NE + e0) * DMODEL];
    const float* et = &g_eemb[(size_t)(i * NE + e1) * DMODEL];
    float* o0 = out + (size_t)b * DMODEL;
    float* o1 = out + ((size_t)N_DOCS * NR + b) * DMODEL;
    for (int dd = threadIdx.x; dd < DMODEL; dd += blockDim.x) {
        o0[dd] = eh[dd];
        o1[dd] = et[dd];
    }
}

// ---------------------------------------------------------------------------
// Kernel 3: rs[i] = ht[i] (256 x 1024) @ seq[i] (1024 x 768) via HMMA bf16
// 3-term split: Ahi*Bhi + Ahi*Blo + Alo*Bhi (fp32 accumulate).
// Block: 256 thr (8 warps), tile BM=128 BN=64 BK=32. Warp = 32x32.
// Grid (768/64=12, 256/128=2, 4) = 96 blocks, single wave.
// Register-prefetch pipeline hides global latency.
// ---------------------------------------------------------------------------
#define BM 128
#define BN 64
#define BK 32
#define AS_STRIDE 20   // u32 per row (16 used + 4 pad): conflict-free frags, 16B-aligned
#define BS_STRIDE 20

__device__ __forceinline__ void mma16816(
    float& c0, float& c1, float& c2, float& c3,
    unsigned a0, unsigned a1, unsigned a2, unsigned a3,
    unsigned b0, unsigned b1)
{
    asm volatile(
        "mma.sync.aligned.m16n8k16.row.col.f32.bf16.bf16.f32 "
        "{%0,%1,%2,%3}, {%4,%5,%6,%7}, {%8,%9}, {%0,%1,%2,%3};\n"
        : "+f"(c0), "+f"(c1), "+f"(c2), "+f"(c3)
        : "r"(a0), "r"(a1), "r"(a2), "r"(a3), "r"(b0), "r"(b1));
}

__global__ __launch_bounds__(256) void k_gemm(
    const float* __restrict__ seq,      // (n, L, d)
    float* __restrict__ out)
{
    __shared__ __align__(16) unsigned As_hi[BM * AS_STRIDE];
    __shared__ __align__(16) unsigned As_lo[BM * AS_STRIDE];
    __shared__ __align__(16) unsigned Bs_hi[BN * BS_STRIDE];
    __shared__ __align__(16) unsigned Bs_lo[BN * BS_STRIDE];

    const int i       = blockIdx.z;
    const int rowBase = blockIdx.y * BM;
    const int colBase = blockIdx.x * BN;

    const int tid  = threadIdx.x;
    const int wid  = tid >> 5;
    const int lane = tid & 31;
    const int g    = lane >> 2;     // 0..7
    const int q    = lane & 3;      // 0..3

    const int warp_m = (wid & 3) * 32;   // 0,32,64,96
    const int warp_n = (wid >> 2) * 32;  // 0,32

    // A (packed) source
    const unsigned* Ah = g_htp_hi + ((size_t)(i * NR + rowBase)) * (LSEQ / 2);
    const unsigned* Al = g_htp_lo + ((size_t)(i * NR + rowBase)) * (LSEQ / 2);
    // B source (fp32)
    const float* B = seq + (size_t)i * LSEQ * DMODEL;

    // Per-thread copy assignments
    // A: 2 uint4 chunks per version; chunk c in {tid, tid+256}: row=c>>2, qd=c&3
    const int ar0 = tid >> 2,          aq0 = (tid & 3) * 4;
    const int ar1 = (tid + 256) >> 2,  aq1 = aq0;
    // B: 4 packed positions p = tid + j*256: n = p&63, k2 = p>>6
    int bn[4], bk2[4];
    #pragma unroll
    for (int j = 0; j < 4; j++) {
        int p = tid + j * 256;
        bn[j]  = p & 63;
        bk2[j] = p >> 6;
    }

    float c[2][4][4];
    #pragma unroll
    for (int mt = 0; mt < 2; mt++)
        #pragma unroll
        for (int nt = 0; nt < 4; nt++)
            #pragma unroll
            for (int r = 0; r < 4; r++) c[mt][nt][r] = 0.f;

    // --- prologue: load tile kk=0 into regs ---
    uint4 rAh0, rAh1, rAl0, rAl1;
    float rB0[4], rB1[4];
    {
        const int kk2 = 0;
        rAh0 = *(const uint4*)&Ah[ar0 * (LSEQ / 2) + kk2 + aq0];
        rAh1 = *(const uint4*)&Ah[ar1 * (LSEQ / 2) + kk2 + aq1];
        rAl0 = *(const uint4*)&Al[ar0 * (LSEQ / 2) + kk2 + aq0];
        rAl1 = *(const uint4*)&Al[ar1 * (LSEQ / 2) + kk2 + aq1];
        #pragma unroll
        for (int j = 0; j < 4; j++) {
            const float* bp = &B[(size_t)(2 * bk2[j]) * DMODEL + colBase + bn[j]];
            rB0[j] = bp[0];
            rB1[j] = bp[DMODEL];
        }
    }

    for (int kk = 0; kk < LSEQ; kk += BK) {
        // ---- store current regs to smem (B: split+pack) ----
        *(uint4*)&As_hi[ar0 * AS_STRIDE + aq0] = rAh0;
        *(uint4*)&As_hi[ar1 * AS_STRIDE + aq1] = rAh1;
        *(uint4*)&As_lo[ar0 * AS_STRIDE + aq0] = rAl0;
        *(uint4*)&As_lo[ar1 * AS_STRIDE + aq1] = rAl1;
        #pragma unroll
        for (int j = 0; j < 4; j++) {
            float h0, l0, h1, l1;
            bsplit(rB0[j], h0, l0);
            bsplit(rB1[j], h1, l1);
            Bs_hi[bn[j] * BS_STRIDE + bk2[j]] = pack2(h0, h1);
            Bs_lo[bn[j] * BS_STRIDE + bk2[j]] = pack2(l0, l1);
        }
        __syncthreads();

        // ---- prefetch next tile into regs (latency hidden by compute) ----
        if (kk + BK < LSEQ) {
            const int kk2 = (kk + BK) >> 1;
            rAh0 = *(const uint4*)&Ah[ar0 * (LSEQ / 2) + kk2 + aq0];
            rAh1 = *(const uint4*)&Ah[ar1 * (LSEQ / 2) + kk2 + aq1];
            rAl0 = *(const uint4*)&Al[ar0 * (LSEQ / 2) + kk2 + aq0];
            rAl1 = *(const uint4*)&Al[ar1 * (LSEQ / 2) + kk2 + aq1];
            #pragma unroll
            for (int j = 0; j < 4; j++) {
                const float* bp = &B[(size_t)(kk + BK + 2 * bk2[j]) * DMODEL
                                     + colBase + bn[j]];
                rB0[j] = bp[0];
                rB1[j] = bp[DMODEL];
            }
        }

        // ---- compute: 2 k16 sub-steps ----
        #pragma unroll
        for (int ks = 0; ks < 2; ks++) {
            const int k2b = ks * 8;
            unsigned ah[2][4], al[2][4];
            #pragma unroll
            for (int mt = 0; mt < 2; mt++) {
                int r0 = (warp_m + mt * 16 + g) * AS_STRIDE + k2b + q;
                int r1 = r0 + 8 * AS_STRIDE;
                ah[mt][0] = As_hi[r0];     ah[mt][1] = As_hi[r1];
                ah[mt][2] = As_hi[r0 + 4]; ah[mt][3] = As_hi[r1 + 4];
                al[mt][0] = As_lo[r0];     al[mt][1] = As_lo[r1];
                al[mt][2] = As_lo[r0 + 4]; al[mt][3] = As_lo[r1 + 4];
            }
            unsigned bh[4][2], bl[4][2];
            #pragma unroll
            for (int nt = 0; nt < 4; nt++) {
                int rb = (warp_n + nt * 8 + g) * BS_STRIDE + k2b + q;
                bh[nt][0] = Bs_hi[rb]; bh[nt][1] = Bs_hi[rb + 4];
                bl[nt][0] = Bs_lo[rb]; bl[nt][1] = Bs_lo[rb + 4];
            }
            #pragma unroll
            for (int mt = 0; mt < 2; mt++)
                #pragma unroll
                for (int nt = 0; nt < 4; nt++) {
                    float* cc = c[mt][nt];
                    mma16816(cc[0], cc[1], cc[2], cc[3],
                             ah[mt][0], ah[mt][1], ah[mt][2], ah[mt][3],
                             bh[nt][0], bh[nt][1]);
                    mma16816(cc[0], cc[1], cc[2], cc[3],
                             ah[mt][0], ah[mt][1], ah[mt][2], ah[mt][3],
                             bl[nt][0], bl[nt][1]);
                    mma16816(cc[0], cc[1], cc[2], cc[3],
                             al[mt][0], al[mt][1], al[mt][2], al[mt][3],
                             bh[nt][0], bh[nt][1]);
                }
        }
        __syncthreads();
    }

    // ---- epilogue: rs block of out ----
    float* O = out + ((size_t)2 * N_DOCS * NR + (size_t)i * NR) * DMODEL;
    #pragma unroll
    for (int mt = 0; mt < 2; mt++) {
        int row0 = rowBase + warp_m + mt * 16 + g;
        #pragma unroll
        for (int nt = 0; nt < 4; nt++) {
            int col = colBase + warp_n + nt * 8 + 2 * q;
            float2 v0 = make_float2(c[mt][nt][0], c[mt][nt][1]);
            float2 v1 = make_float2(c[mt][nt][2], c[mt][nt][3]);
            *(float2*)&O[(size_t)row0 * DMODEL + col]       = v0;
            *(float2*)&O[(size_t)(row0 + 8) * DMODEL + col] = v1;
        }
    }
}

// ---------------------------------------------------------------------------
extern "C" void kernel_launch(void* const* d_in, const int* in_sizes, int n_in,
                              void* d_out, int out_size)
{
    const float* seq   = (const float*)d_in[0];   // (4,1024,768) f32
    const float* att   = (const float*)d_in[1];   // (4,12,1024,1024) f32
    const int*   mpos  = (const int*)  d_in[2];   // (4,32,4) i32
    const float* mmask = (const float*)d_in[3];   // (4,32,4) f32
    const int*   hts   = (const int*)  d_in[4];   // (4,256,2) i32
    float* out = (float*)d_out;                   // (3, 4*256, 768) f32

    k_prep <<<N_DOCS * NE * NHEAD + N_DOCS * NE, 256>>>(seq, att, mpos, mmask);
    k_htatt<<<N_DOCS * NR, 256>>>(hts, out);
    k_gemm <<<dim3(DMODEL / BN, NR / BM, N_DOCS), 256>>>(seq, out);
}